// round 14
// baseline (speedup 1.0000x reference)
#include <cuda_runtime.h>
#include <cuda_fp16.h>

// FALayer, dst-bucketed, serial pipeline:
//   z[t] = d[t] * sum_e (g+y)*0.5 * (h[s]*d[s])      [d folded into fp16 rows]
//   proj(+fp16 h*d copy, +fused REDG hist, pd includes bias)
//   -> scan (decoupled lookback; zeroes deg for next run -> no memset)
//   -> scatter (scalar 4B random loads) -> gather (f32x2 packed FMA)
// Inputs: 0 h[N,128]f32  1 d[N]f32  2 yes_no[E]f32  3 gate_w[1,256]f32
//         4 gate_b[1]f32 5 yes_w f32 6 no_w f32  7 src[E]i32  8 dst[E]i32
// Output: z[N,128]f32

#define D 128
#define MAX_N 100352
#define MAX_E 1605632
#define SCAN_T 512
#define SCAN_K 8
#define SCAN_TILE (SCAN_T * SCAN_K)
#define MAX_SCAN_BLOCKS 64

__device__ float g_pd[MAX_N];              // p_dst + gate_b
__device__ float g_ps[MAX_N];              // p_src
__device__ int g_deg[MAX_N];               // zero-init at load; scan re-zeroes
__device__ int g_offs[MAX_N + 1];
__device__ int g_cursor[MAX_N];
__device__ volatile unsigned long long g_state[MAX_SCAN_BLOCKS];
__device__ long long g_pairs[MAX_E];                 // lo32 src, hi32 coef bits
__device__ __half2 g_h2[(size_t)MAX_N * (D / 2)];    // fp16 (h * d) copy

// ---- proj + fp16 (h*d) convert + fused histogram (no-return REDG) + state zero
__global__ void proj_kernel(const float* __restrict__ h,
                            const float* __restrict__ dnorm,
                            const float* __restrict__ gate_w,
                            const float* __restrict__ gate_b,
                            const int* __restrict__ dst,
                            int n_nodes, int n_edges) {
    int gtid = blockIdx.x * blockDim.x + threadIdx.x;

    if (gtid < MAX_SCAN_BLOCKS) g_state[gtid] = 0ULL;

    // fused histogram (deg zeroed by previous scan / static init)
    for (int e = gtid; e < n_edges; e += gridDim.x * blockDim.x)
        atomicAdd(&g_deg[dst[e]], 1);

    int warp = gtid >> 5;
    int lane = threadIdx.x & 31;
    if (warp >= n_nodes) return;

    const float4* hrow = reinterpret_cast<const float4*>(h + (size_t)warp * D);
    const float4* wd = reinterpret_cast<const float4*>(gate_w);
    const float4* ws = reinterpret_cast<const float4*>(gate_w + D);

    float4 hv = hrow[lane];
    float4 wdv = wd[lane];
    float4 wsv = ws[lane];

    float dn = dnorm[warp];
    __half2 a = __floats2half2_rn(hv.x * dn, hv.y * dn);
    __half2 b = __floats2half2_rn(hv.z * dn, hv.w * dn);
    size_t base = (size_t)warp * (D / 2) + lane * 2;
    g_h2[base] = a;
    g_h2[base + 1] = b;

    float pd = hv.x * wdv.x + hv.y * wdv.y + hv.z * wdv.z + hv.w * wdv.w;
    float ps = hv.x * wsv.x + hv.y * wsv.y + hv.z * wsv.z + hv.w * wsv.w;

    #pragma unroll
    for (int off = 16; off > 0; off >>= 1) {
        pd += __shfl_xor_sync(0xFFFFFFFF, pd, off);
        ps += __shfl_xor_sync(0xFFFFFFFF, ps, off);
    }
    if (lane == 0) {
        g_pd[warp] = pd + gate_b[0];
        g_ps[warp] = ps;
    }
}

// ------- single-kernel exclusive scan with decoupled lookback (+deg zeroing)
__global__ void scan_kernel(int n_nodes, int n_edges) {
    __shared__ int wsum[SCAN_T / 32];
    __shared__ int round_total;
    __shared__ int block_base;

    int b = blockIdx.x;
    int t = threadIdx.x;
    int lane = t & 31;
    int wid = t >> 5;

    int excl[SCAN_K];
    int running = 0;

    #pragma unroll
    for (int k = 0; k < SCAN_K; k++) {
        int i = b * SCAN_TILE + k * SCAN_T + t;
        int v = 0;
        if (i < n_nodes) {
            v = g_deg[i];
            g_deg[i] = 0;           // re-establish invariant for next run
        }

        int x = v;
        #pragma unroll
        for (int off = 1; off < 32; off <<= 1) {
            int u = __shfl_up_sync(0xFFFFFFFF, x, off);
            if (lane >= off) x += u;
        }
        if (lane == 31) wsum[wid] = x;
        __syncthreads();

        if (wid == 0 && lane < SCAN_T / 32) {
            int w = wsum[lane];
            int y = w;
            #pragma unroll
            for (int off = 1; off < SCAN_T / 32; off <<= 1) {
                int u = __shfl_up_sync(0xFFFF, y, off);
                if (lane >= off) y += u;
            }
            wsum[lane] = y - w;
            if (lane == SCAN_T / 32 - 1) round_total = y;
        }
        __syncthreads();

        excl[k] = (x - v) + wsum[wid] + running;
        running += round_total;
        __syncthreads();
    }

    if (t == 0) {
        if (b == 0) {
            g_state[0] = (2ULL << 32) | (unsigned int)running;
            block_base = 0;
        } else {
            g_state[b] = (1ULL << 32) | (unsigned int)running;
            int base = 0;
            int j = b - 1;
            while (true) {
                unsigned long long s;
                do { s = g_state[j]; } while ((s >> 32) == 0);
                base += (int)(unsigned int)s;
                if ((s >> 32) == 2ULL) break;
                j--;
            }
            g_state[b] = (2ULL << 32) | (unsigned int)(base + running);
            block_base = base;
        }
    }
    __syncthreads();

    int base = block_base;
    #pragma unroll
    for (int k = 0; k < SCAN_K; k++) {
        int i = b * SCAN_TILE + k * SCAN_T + t;
        if (i < n_nodes) {
            int e = excl[k] + base;
            g_offs[i] = e;
            g_cursor[i] = e;
        }
    }
    if (b == 0 && t == 0) g_offs[n_nodes] = n_edges;
}

// -------- scatter: two scalar 4B random loads, cursor atomic, 8B store
__global__ void scatter_kernel(const float* __restrict__ yes_no,
                               const float* __restrict__ yes_w,
                               const float* __restrict__ no_w,
                               const int* __restrict__ src,
                               const int* __restrict__ dst,
                               int n_edges) {
    int e = blockIdx.x * blockDim.x + threadIdx.x;
    if (e >= n_edges) return;

    int s = src[e];
    int t = dst[e];

    float pd = g_pd[t];
    float ps = g_ps[s];

    float yn = yes_no[e];
    float g = tanhf(pd + ps);
    float y = tanhf(yn * yes_w[0] + (1.0f - yn) * no_w[0]);
    float coef = (g + y) * 0.5f;

    int pos = atomicAdd(&g_cursor[t], 1);
    long long packed = ((long long)__float_as_int(coef) << 32) | (unsigned int)s;
    g_pairs[pos] = packed;
}

// ---------------------------------------------------------------- gather
// 16 lanes per node (2 nodes per warp), unroll 4, packed f32x2 FMA (FFMA2).
__device__ __forceinline__ void fma_row16(unsigned long long acc[4],
                                          long long p, unsigned int sub16) {
    int s = (int)(unsigned int)(p & 0xffffffffLL);
    float c = __int_as_float((int)(p >> 32));
    unsigned long long c2;
    asm("mov.b64 %0, {%1, %1};" : "=l"(c2) : "f"(c));

    unsigned int off = (unsigned int)s * 256u + sub16;
    uint4 raw = *reinterpret_cast<const uint4*>(
        reinterpret_cast<const char*>(g_h2) + off);
    float2 f0 = __half22float2(*reinterpret_cast<__half2*>(&raw.x));
    float2 f1 = __half22float2(*reinterpret_cast<__half2*>(&raw.y));
    float2 f2 = __half22float2(*reinterpret_cast<__half2*>(&raw.z));
    float2 f3 = __half22float2(*reinterpret_cast<__half2*>(&raw.w));

    unsigned long long v0, v1, v2, v3;
    asm("mov.b64 %0, {%1, %2};" : "=l"(v0) : "f"(f0.x), "f"(f0.y));
    asm("mov.b64 %0, {%1, %2};" : "=l"(v1) : "f"(f1.x), "f"(f1.y));
    asm("mov.b64 %0, {%1, %2};" : "=l"(v2) : "f"(f2.x), "f"(f2.y));
    asm("mov.b64 %0, {%1, %2};" : "=l"(v3) : "f"(f3.x), "f"(f3.y));

    asm("fma.rn.f32x2 %0, %1, %2, %0;" : "+l"(acc[0]) : "l"(v0), "l"(c2));
    asm("fma.rn.f32x2 %0, %1, %2, %0;" : "+l"(acc[1]) : "l"(v1), "l"(c2));
    asm("fma.rn.f32x2 %0, %1, %2, %0;" : "+l"(acc[2]) : "l"(v2), "l"(c2));
    asm("fma.rn.f32x2 %0, %1, %2, %0;" : "+l"(acc[3]) : "l"(v3), "l"(c2));
}

__global__ void gather_kernel(const float* __restrict__ dnorm,
                              float* __restrict__ z, int n_nodes) {
    int gwarp = (blockIdx.x * blockDim.x + threadIdx.x) >> 5;
    int lane = threadIdx.x & 31;
    int half = lane >> 4;
    int sub = lane & 15;
    unsigned int sub16 = (unsigned int)sub * 16u;
    int node = gwarp * 2 + half;
    if (node >= n_nodes) return;

    int start = g_offs[node];
    int end = g_offs[node + 1];
    float dt = dnorm[node];
    unsigned long long dt2;
    asm("mov.b64 %0, {%1, %1};" : "=l"(dt2) : "f"(dt));

    unsigned long long acc[4] = {0ULL, 0ULL, 0ULL, 0ULL};

    int i = start;
    for (; i + 3 < end; i += 4) {
        long long p0 = g_pairs[i];
        long long p1 = g_pairs[i + 1];
        long long p2 = g_pairs[i + 2];
        long long p3 = g_pairs[i + 3];
        fma_row16(acc, p0, sub16);
        fma_row16(acc, p1, sub16);
        fma_row16(acc, p2, sub16);
        fma_row16(acc, p3, sub16);
    }
    for (; i < end; i++) {
        fma_row16(acc, g_pairs[i], sub16);
    }

    // scale by d[t] (packed), then store 2 float4s
    #pragma unroll
    for (int k = 0; k < 4; k++)
        asm("mul.rn.f32x2 %0, %0, %1;" : "+l"(acc[k]) : "l"(dt2));

    float r0, r1, r2, r3, r4, r5, r6, r7;
    asm("mov.b64 {%0, %1}, %2;" : "=f"(r0), "=f"(r1) : "l"(acc[0]));
    asm("mov.b64 {%0, %1}, %2;" : "=f"(r2), "=f"(r3) : "l"(acc[1]));
    asm("mov.b64 {%0, %1}, %2;" : "=f"(r4), "=f"(r5) : "l"(acc[2]));
    asm("mov.b64 {%0, %1}, %2;" : "=f"(r6), "=f"(r7) : "l"(acc[3]));

    float4* zrow = reinterpret_cast<float4*>(z + (size_t)node * D);
    zrow[sub * 2]     = make_float4(r0, r1, r2, r3);
    zrow[sub * 2 + 1] = make_float4(r4, r5, r6, r7);
}

extern "C" void kernel_launch(void* const* d_in, const int* in_sizes, int n_in,
                              void* d_out, int out_size) {
    const float* h       = (const float*)d_in[0];
    const float* dnorm   = (const float*)d_in[1];
    const float* yes_no  = (const float*)d_in[2];
    const float* gate_w  = (const float*)d_in[3];
    const float* gate_b  = (const float*)d_in[4];
    const float* yes_w   = (const float*)d_in[5];
    const float* no_w    = (const float*)d_in[6];
    const int* src       = (const int*)d_in[7];
    const int* dst       = (const int*)d_in[8];
    float* z = (float*)d_out;

    int n_nodes = in_sizes[1];
    int n_edges = in_sizes[2];
    int scan_blocks = (n_nodes + SCAN_TILE - 1) / SCAN_TILE;

    {   // proj + fp16 (h*d) + fused histogram (deg zeroed by prior scan)
        int blocks = (n_nodes + 7) / 8;
        proj_kernel<<<blocks, 256>>>(h, dnorm, gate_w, gate_b, dst,
                                     n_nodes, n_edges);
    }
    scan_kernel<<<scan_blocks, SCAN_T>>>(n_nodes, n_edges);
    {   // scatter with scalar random loads
        int blocks = (n_edges + 255) / 256;
        scatter_kernel<<<blocks, 256>>>(yes_no, yes_w, no_w, src, dst, n_edges);
    }
    {   // gather (packed FFMA2)
        int warps_needed = (n_nodes + 1) / 2;
        int blocks = (warps_needed + 7) / 8;
        gather_kernel<<<blocks, 256>>>(dnorm, z, n_nodes);
    }
}

// round 15
// speedup vs baseline: 1.0990x; 1.0990x over previous
#include <cuda_runtime.h>
#include <cuda_fp16.h>

// FALayer, dst-bucketed, serial pipeline (R13 hot kernels + no-memset):
//   z[t] = d[t] * sum_e (g+y)*0.5 * (h[s]*d[s])      [d folded into fp16 rows]
//   proj(+fp16 h*d copy, +fused REDG hist, pd includes bias)
//   -> scan (decoupled lookback; zeroes deg for next run -> no memset launch)
//   -> scatter (scalar 4B random loads) -> gather (scalar FMA, 16 lanes/node)
// Inputs: 0 h[N,128]f32  1 d[N]f32  2 yes_no[E]f32  3 gate_w[1,256]f32
//         4 gate_b[1]f32 5 yes_w f32 6 no_w f32  7 src[E]i32  8 dst[E]i32
// Output: z[N,128]f32

#define D 128
#define MAX_N 100352
#define MAX_E 1605632
#define SCAN_T 512
#define SCAN_K 8
#define SCAN_TILE (SCAN_T * SCAN_K)
#define MAX_SCAN_BLOCKS 64

__device__ float g_pd[MAX_N];              // p_dst + gate_b
__device__ float g_ps[MAX_N];              // p_src
__device__ int g_deg[MAX_N];               // zero-init at load; scan re-zeroes
__device__ int g_offs[MAX_N + 1];
__device__ int g_cursor[MAX_N];
__device__ volatile unsigned long long g_state[MAX_SCAN_BLOCKS];
__device__ long long g_pairs[MAX_E];                 // lo32 src, hi32 coef bits
__device__ __half2 g_h2[(size_t)MAX_N * (D / 2)];    // fp16 (h * d) copy

// ---- proj + fp16 (h*d) convert + fused histogram (no-return REDG) + state zero
__global__ void proj_kernel(const float* __restrict__ h,
                            const float* __restrict__ dnorm,
                            const float* __restrict__ gate_w,
                            const float* __restrict__ gate_b,
                            const int* __restrict__ dst,
                            int n_nodes, int n_edges) {
    int gtid = blockIdx.x * blockDim.x + threadIdx.x;

    if (gtid < MAX_SCAN_BLOCKS) g_state[gtid] = 0ULL;

    // fused histogram (deg zeroed by previous scan / static init)
    for (int e = gtid; e < n_edges; e += gridDim.x * blockDim.x)
        atomicAdd(&g_deg[dst[e]], 1);

    int warp = gtid >> 5;
    int lane = threadIdx.x & 31;
    if (warp >= n_nodes) return;

    const float4* hrow = reinterpret_cast<const float4*>(h + (size_t)warp * D);
    const float4* wd = reinterpret_cast<const float4*>(gate_w);
    const float4* ws = reinterpret_cast<const float4*>(gate_w + D);

    float4 hv = hrow[lane];
    float4 wdv = wd[lane];
    float4 wsv = ws[lane];

    float dn = dnorm[warp];
    __half2 a = __floats2half2_rn(hv.x * dn, hv.y * dn);
    __half2 b = __floats2half2_rn(hv.z * dn, hv.w * dn);
    size_t base = (size_t)warp * (D / 2) + lane * 2;
    g_h2[base] = a;
    g_h2[base + 1] = b;

    float pd = hv.x * wdv.x + hv.y * wdv.y + hv.z * wdv.z + hv.w * wdv.w;
    float ps = hv.x * wsv.x + hv.y * wsv.y + hv.z * wsv.z + hv.w * wsv.w;

    #pragma unroll
    for (int off = 16; off > 0; off >>= 1) {
        pd += __shfl_xor_sync(0xFFFFFFFF, pd, off);
        ps += __shfl_xor_sync(0xFFFFFFFF, ps, off);
    }
    if (lane == 0) {
        g_pd[warp] = pd + gate_b[0];
        g_ps[warp] = ps;
    }
}

// ------- single-kernel exclusive scan with decoupled lookback (+deg zeroing)
__global__ void scan_kernel(int n_nodes, int n_edges) {
    __shared__ int wsum[SCAN_T / 32];
    __shared__ int round_total;
    __shared__ int block_base;

    int b = blockIdx.x;
    int t = threadIdx.x;
    int lane = t & 31;
    int wid = t >> 5;

    int excl[SCAN_K];
    int running = 0;

    #pragma unroll
    for (int k = 0; k < SCAN_K; k++) {
        int i = b * SCAN_TILE + k * SCAN_T + t;
        int v = 0;
        if (i < n_nodes) {
            v = g_deg[i];
            g_deg[i] = 0;           // re-establish invariant for next run
        }

        int x = v;
        #pragma unroll
        for (int off = 1; off < 32; off <<= 1) {
            int u = __shfl_up_sync(0xFFFFFFFF, x, off);
            if (lane >= off) x += u;
        }
        if (lane == 31) wsum[wid] = x;
        __syncthreads();

        if (wid == 0 && lane < SCAN_T / 32) {
            int w = wsum[lane];
            int y = w;
            #pragma unroll
            for (int off = 1; off < SCAN_T / 32; off <<= 1) {
                int u = __shfl_up_sync(0xFFFF, y, off);
                if (lane >= off) y += u;
            }
            wsum[lane] = y - w;
            if (lane == SCAN_T / 32 - 1) round_total = y;
        }
        __syncthreads();

        excl[k] = (x - v) + wsum[wid] + running;
        running += round_total;
        __syncthreads();
    }

    if (t == 0) {
        if (b == 0) {
            g_state[0] = (2ULL << 32) | (unsigned int)running;
            block_base = 0;
        } else {
            g_state[b] = (1ULL << 32) | (unsigned int)running;
            int base = 0;
            int j = b - 1;
            while (true) {
                unsigned long long s;
                do { s = g_state[j]; } while ((s >> 32) == 0);
                base += (int)(unsigned int)s;
                if ((s >> 32) == 2ULL) break;
                j--;
            }
            g_state[b] = (2ULL << 32) | (unsigned int)(base + running);
            block_base = base;
        }
    }
    __syncthreads();

    int base = block_base;
    #pragma unroll
    for (int k = 0; k < SCAN_K; k++) {
        int i = b * SCAN_TILE + k * SCAN_T + t;
        if (i < n_nodes) {
            int e = excl[k] + base;
            g_offs[i] = e;
            g_cursor[i] = e;
        }
    }
    if (b == 0 && t == 0) g_offs[n_nodes] = n_edges;
}

// -------- scatter: two scalar 4B random loads, cursor atomic, 8B store
__global__ void scatter_kernel(const float* __restrict__ yes_no,
                               const float* __restrict__ yes_w,
                               const float* __restrict__ no_w,
                               const int* __restrict__ src,
                               const int* __restrict__ dst,
                               int n_edges) {
    int e = blockIdx.x * blockDim.x + threadIdx.x;
    if (e >= n_edges) return;

    int s = src[e];
    int t = dst[e];

    float pd = g_pd[t];
    float ps = g_ps[s];

    float yn = yes_no[e];
    float g = tanhf(pd + ps);
    float y = tanhf(yn * yes_w[0] + (1.0f - yn) * no_w[0]);
    float coef = (g + y) * 0.5f;

    int pos = atomicAdd(&g_cursor[t], 1);
    long long packed = ((long long)__float_as_int(coef) << 32) | (unsigned int)s;
    g_pairs[pos] = packed;
}

// ---------------------------------------------------------------- gather
// 16 lanes per node (2 nodes per warp), unroll 4, scalar FMA (R13-verified).
__device__ __forceinline__ void fma_row16(float acc[8], long long p,
                                          unsigned int sub16) {
    int s = (int)(unsigned int)(p & 0xffffffffLL);
    float c = __int_as_float((int)(p >> 32));
    unsigned int off = (unsigned int)s * 256u + sub16;
    uint4 raw = *reinterpret_cast<const uint4*>(
        reinterpret_cast<const char*>(g_h2) + off);
    float2 f0 = __half22float2(*reinterpret_cast<__half2*>(&raw.x));
    float2 f1 = __half22float2(*reinterpret_cast<__half2*>(&raw.y));
    float2 f2 = __half22float2(*reinterpret_cast<__half2*>(&raw.z));
    float2 f3 = __half22float2(*reinterpret_cast<__half2*>(&raw.w));
    acc[0] += f0.x * c; acc[1] += f0.y * c;
    acc[2] += f1.x * c; acc[3] += f1.y * c;
    acc[4] += f2.x * c; acc[5] += f2.y * c;
    acc[6] += f3.x * c; acc[7] += f3.y * c;
}

__global__ void gather_kernel(const float* __restrict__ dnorm,
                              float* __restrict__ z, int n_nodes) {
    int gwarp = (blockIdx.x * blockDim.x + threadIdx.x) >> 5;
    int lane = threadIdx.x & 31;
    int half = lane >> 4;
    int sub = lane & 15;
    unsigned int sub16 = (unsigned int)sub * 16u;
    int node = gwarp * 2 + half;
    if (node >= n_nodes) return;

    int start = g_offs[node];
    int end = g_offs[node + 1];
    float dt = dnorm[node];

    float acc[8] = {0.f, 0.f, 0.f, 0.f, 0.f, 0.f, 0.f, 0.f};

    int i = start;
    for (; i + 3 < end; i += 4) {
        long long p0 = g_pairs[i];
        long long p1 = g_pairs[i + 1];
        long long p2 = g_pairs[i + 2];
        long long p3 = g_pairs[i + 3];
        fma_row16(acc, p0, sub16);
        fma_row16(acc, p1, sub16);
        fma_row16(acc, p2, sub16);
        fma_row16(acc, p3, sub16);
    }
    for (; i < end; i++) {
        fma_row16(acc, g_pairs[i], sub16);
    }

    float4* zrow = reinterpret_cast<float4*>(z + (size_t)node * D);
    zrow[sub * 2]     = make_float4(acc[0] * dt, acc[1] * dt,
                                    acc[2] * dt, acc[3] * dt);
    zrow[sub * 2 + 1] = make_float4(acc[4] * dt, acc[5] * dt,
                                    acc[6] * dt, acc[7] * dt);
}

extern "C" void kernel_launch(void* const* d_in, const int* in_sizes, int n_in,
                              void* d_out, int out_size) {
    const float* h       = (const float*)d_in[0];
    const float* dnorm   = (const float*)d_in[1];
    const float* yes_no  = (const float*)d_in[2];
    const float* gate_w  = (const float*)d_in[3];
    const float* gate_b  = (const float*)d_in[4];
    const float* yes_w   = (const float*)d_in[5];
    const float* no_w    = (const float*)d_in[6];
    const int* src       = (const int*)d_in[7];
    const int* dst       = (const int*)d_in[8];
    float* z = (float*)d_out;

    int n_nodes = in_sizes[1];
    int n_edges = in_sizes[2];
    int scan_blocks = (n_nodes + SCAN_TILE - 1) / SCAN_TILE;

    {   // proj + fp16 (h*d) + fused histogram (deg zeroed by prior scan)
        int blocks = (n_nodes + 7) / 8;
        proj_kernel<<<blocks, 256>>>(h, dnorm, gate_w, gate_b, dst,
                                     n_nodes, n_edges);
    }
    scan_kernel<<<scan_blocks, SCAN_T>>>(n_nodes, n_edges);
    {   // scatter with scalar random loads
        int blocks = (n_edges + 255) / 256;
        scatter_kernel<<<blocks, 256>>>(yes_no, yes_w, no_w, src, dst, n_edges);
    }
    {   // gather (scalar FMA, verified fastest)
        int warps_needed = (n_nodes + 1) / 2;
        int blocks = (warps_needed + 7) / 8;
        gather_kernel<<<blocks, 256>>>(dnorm, z, n_nodes);
    }
}